// round 1
// baseline (speedup 1.0000x reference)
#include <cuda_runtime.h>
#include <cstdint>
#include <cstddef>

#define NN 100000
#define EE 800000

// ---------------- device scratch (static: no runtime allocation) ----------------
__device__ float g_key[(size_t)NN * 128];
__device__ float g_val[(size_t)NN * 128];
__device__ float g_qry[(size_t)NN * 128];
__device__ float g_qk [(size_t)NN * 64];
__device__ float g_ex [(size_t)EE * 4];
__device__ float g_den[(size_t)NN * 4];
__device__ float g_wrbfc[42 * 32];
__device__ float g_wsbfc[16 * 32];

// ---------------- K0: combine weight pairs ----------------
__global__ void k_combine_rbf(const float* __restrict__ w0, const float* __restrict__ w1) {
    int i = blockIdx.x * blockDim.x + threadIdx.x;
    if (i >= 42 * 32) return;
    int d = i >> 5, c = i & 31;
    float s = 0.f;
#pragma unroll
    for (int m = 0; m < 32; m++) s += w0[d * 32 + m] * w1[m * 32 + c];
    g_wrbfc[i] = s;
}

__global__ void k_combine_sbf(const float* __restrict__ w0, const float* __restrict__ w1) {
    int i = blockIdx.x * blockDim.x + threadIdx.x;
    if (i >= 16 * 32) return;
    int d = i >> 5, c = i & 31;
    float s = 0.f;
#pragma unroll
    for (int m = 0; m < 32; m++) s += w0[d * 32 + m] * w1[m * 32 + c];
    g_wsbfc[i] = s;
}

// ---------------- K1: node kernel ----------------
// lane = node within a 32-node tile; all weight reads are smem broadcasts.
// Shared layout (floats):
//   s_wk 0..4095 | s_wq 4096 | s_wv 8192 | s_ws 12288 | s_ekT 16384 (+2048)
//   s_rc 18432 (+1344) | s_b 19776 (+512: bk,bq,bv,bs) | stage 20288 (+12*1440)
#define K1_WARPS 12
#define K1_SMEM_FLOATS (20288 + K1_WARPS * 1440)

__global__ void __launch_bounds__(K1_WARPS * 32)
k_node(const float* __restrict__ x, const float* __restrict__ rbf,
       const float* __restrict__ wk, const float* __restrict__ bk,
       const float* __restrict__ wq, const float* __restrict__ bq,
       const float* __restrict__ wv, const float* __restrict__ bv,
       const float* __restrict__ wsk, const float* __restrict__ bsk,
       const float* __restrict__ wek, float* __restrict__ out) {
    extern __shared__ float sh[];
    float* s_wk  = sh;
    float* s_wq  = sh + 4096;
    float* s_wv  = sh + 8192;
    float* s_ws  = sh + 12288;
    float* s_ekT = sh + 16384;   // ekT[j*16+d] = wek[d*128+j]
    float* s_rc  = sh + 18432;
    float* s_b   = sh + 19776;
    float* s_stg = sh + 20288;

    const int tid = threadIdx.x, nt = blockDim.x;
    for (int i = tid; i < 4096; i += nt) {
        s_wk[i] = wk[i]; s_wq[i] = wq[i]; s_wv[i] = wv[i]; s_ws[i] = wsk[i];
    }
    for (int i = tid; i < 2048; i += nt) {
        int j = i >> 4, d = i & 15;
        s_ekT[i] = wek[d * 128 + j];
    }
    for (int i = tid; i < 1344; i += nt) s_rc[i] = g_wrbfc[i];
    for (int i = tid; i < 512; i += nt) {
        int w = i >> 7, c = i & 127;
        s_b[i] = (w == 0) ? bk[c] : (w == 1) ? bq[c] : (w == 2) ? bv[c] : bsk[c];
    }
    __syncthreads();

    const int warpid = tid >> 5;
    const int lane   = tid & 31;
    const int tile   = blockIdx.x * K1_WARPS + warpid;
    if (tile >= (NN / 32)) return;
    const int n0 = tile * 32;
    const int n  = n0 + lane;
    float* wb = s_stg + warpid * 1440;

    // ---- stage x rows (coalesced) -> per-lane registers ----
    for (int r = 0; r < 32; r++)
        wb[r * 33 + lane] = x[(size_t)(n0 + r) * 32 + lane];
    __syncwarp();
    float xr[32];
#pragma unroll
    for (int c = 0; c < 32; c++) xr[c] = wb[lane * 33 + c];
    __syncwarp();

    // ---- stage rbf rows ----
    for (int r = 0; r < 32; r++) {
        wb[r * 45 + lane] = rbf[(size_t)(n0 + r) * 42 + lane];
        if (lane < 10) wb[r * 45 + 32 + lane] = rbf[(size_t)(n0 + r) * 42 + 32 + lane];
    }
    __syncwarp();
    float rr[42];
#pragma unroll
    for (int d = 0; d < 42; d++) rr[d] = wb[lane * 45 + d];

    // ---- rbf_filter (combined) -> x_src ----
    float xs[32];
#pragma unroll
    for (int ct8 = 0; ct8 < 8; ct8++) {
        float4 a = make_float4(0.f, 0.f, 0.f, 0.f);
#pragma unroll
        for (int d = 0; d < 42; d++) {
            float4 w = *(const float4*)&s_rc[d * 32 + ct8 * 4];
            a.x += rr[d] * w.x; a.y += rr[d] * w.y;
            a.z += rr[d] * w.z; a.w += rr[d] * w.w;
        }
        xs[ct8 * 4 + 0] = a.x * xr[ct8 * 4 + 0];
        xs[ct8 * 4 + 1] = a.y * xr[ct8 * 4 + 1];
        xs[ct8 * 4 + 2] = a.z * xr[ct8 * 4 + 2];
        xs[ct8 * 4 + 3] = a.w * xr[ct8 * 4 + 3];
    }

    // ---- main projections + folded qk ----
    float qk[16];
#pragma unroll 1
    for (int ct = 0; ct < 32; ct++) {
        const int ch = ct * 4;
        if ((ct & 7) == 0) {
#pragma unroll
            for (int i = 0; i < 16; i++) qk[i] = 0.f;
        }
        float4 ak  = *(const float4*)&s_b[ch];
        float4 aq  = *(const float4*)&s_b[128 + ch];
        float4 av  = *(const float4*)&s_b[256 + ch];
        float4 as2 = *(const float4*)&s_b[384 + ch];
#pragma unroll
        for (int c = 0; c < 32; c++) {
            float4 w1 = *(const float4*)&s_wk[c * 128 + ch];
            float4 w2 = *(const float4*)&s_wq[c * 128 + ch];
            float4 w3 = *(const float4*)&s_wv[c * 128 + ch];
            float4 w4 = *(const float4*)&s_ws[c * 128 + ch];
            float a = xs[c], b = xr[c];
            ak.x  += a * w1.x; ak.y  += a * w1.y; ak.z  += a * w1.z; ak.w  += a * w1.w;
            aq.x  += b * w2.x; aq.y  += b * w2.y; aq.z  += b * w2.z; aq.w  += b * w2.w;
            av.x  += a * w3.x; av.y  += a * w3.y; av.z  += a * w3.z; av.w  += a * w3.w;
            as2.x += b * w4.x; as2.y += b * w4.y; as2.z += b * w4.z; as2.w += b * w4.w;
        }
        *(float4*)&g_key[(size_t)n * 128 + ch] = ak;
        *(float4*)&g_val[(size_t)n * 128 + ch] = av;
        *(float4*)&g_qry[(size_t)n * 128 + ch] = aq;
        *(float4*)&out  [(size_t)n * 128 + ch] = as2;

        // qk[h][d] += q[ch+u] * ekT[(ch+u)*16 + d]
        float qa[4] = {aq.x, aq.y, aq.z, aq.w};
#pragma unroll
        for (int u = 0; u < 4; u++) {
#pragma unroll
            for (int dt = 0; dt < 4; dt++) {
                float4 ekv = *(const float4*)&s_ekT[(ch + u) * 16 + dt * 4];
                qk[dt * 4 + 0] += qa[u] * ekv.x;
                qk[dt * 4 + 1] += qa[u] * ekv.y;
                qk[dt * 4 + 2] += qa[u] * ekv.z;
                qk[dt * 4 + 3] += qa[u] * ekv.w;
            }
        }
        if ((ct & 7) == 7) {
            const int h = ct >> 3;
#pragma unroll
            for (int dt = 0; dt < 4; dt++)
                *(float4*)&g_qk[(size_t)n * 64 + h * 16 + dt * 4] =
                    make_float4(qk[dt * 4 + 0], qk[dt * 4 + 1], qk[dt * 4 + 2], qk[dt * 4 + 3]);
        }
    }
    *(float4*)&g_den[(size_t)n * 4] = make_float4(0.f, 0.f, 0.f, 0.f);
}

// ---------------- K2: edge alpha (8 lanes/edge, 4 edges/warp) ----------------
__global__ void __launch_bounds__(256)
k_alpha(const float* __restrict__ ea, const int* __restrict__ ei) {
    const int gw   = (blockIdx.x * blockDim.x + threadIdx.x) >> 5;
    const int lane = threadIdx.x & 31;
    const int g = lane >> 3, t = lane & 7;
    const int e = gw * 4 + g;
    if (e >= EE) return;
    const int src = ei[e];
    const int dst = ei[EE + e];
    const int h = t >> 1, half = t & 1;

    const float4* qp = (const float4*)(g_qry + (size_t)dst * 128 + h * 32 + half * 16);
    const float4* kp = (const float4*)(g_key + (size_t)src * 128 + h * 32 + half * 16);
    float s = 0.f;
#pragma unroll
    for (int k = 0; k < 4; k++) {
        float4 q = qp[k], kk = kp[k];
        s += q.x * kk.x + q.y * kk.y + q.z * kk.z + q.w * kk.w;
    }
    const float4* qkp = (const float4*)(g_qk + (size_t)dst * 64 + h * 16 + half * 8);
    const float4* eap = (const float4*)(ea + (size_t)e * 16 + half * 8);
    float4 a0 = qkp[0], b0 = eap[0];
    float4 a1 = qkp[1], b1 = eap[1];
    s += a0.x * b0.x + a0.y * b0.y + a0.z * b0.z + a0.w * b0.w;
    s += a1.x * b1.x + a1.y * b1.y + a1.z * b1.z + a1.w * b1.w;

    s += __shfl_xor_sync(0xffffffffu, s, 1);
    if (half == 0) {
        float ex = __expf(s * 0.17677669529663687f);  // 1/sqrt(32)
        g_ex[(size_t)e * 4 + h] = ex;
        atomicAdd(&g_den[(size_t)dst * 4 + h], ex);
    }
}

// ---------------- K3: message + aggregation (8 lanes/edge, 4 edges/warp) ----------------
__global__ void __launch_bounds__(256)
k_msg(const float* __restrict__ ea, const float* __restrict__ sbf,
      const int* __restrict__ ei, const float* __restrict__ wev,
      float* __restrict__ out) {
    __shared__ float s_ev[16 * 128];
    __shared__ float s_sc[16 * 32];
    __shared__ float s_buf[8][352];   // per warp: sbf 4 edges x 64 @pitch68 (=272), ea 4x16 @pitch20 (=80)

    for (int i = threadIdx.x; i < 2048; i += 256) s_ev[i] = wev[i];
    for (int i = threadIdx.x; i < 512;  i += 256) s_sc[i] = g_wsbfc[i];
    __syncthreads();

    const int warpid = threadIdx.x >> 5;
    const int lane   = threadIdx.x & 31;
    const int g = lane >> 3, t = lane & 7;
    const int warps_total = gridDim.x * 8;
    float* sb = s_buf[warpid];

    for (int tile = blockIdx.x * 8 + warpid; tile < EE / 4; tile += warps_total) {
        const int base = tile * 4;
        // stage sbf (4 edges x 64 floats, contiguous in gmem)
        const float4* sp = (const float4*)(sbf + (size_t)base * 64);
        {
            int idx = lane * 4;                // elems 0..127
            *(float4*)&sb[(idx >> 6) * 68 + (idx & 63)] = sp[lane];
            idx = 128 + lane * 4;              // elems 128..255
            *(float4*)&sb[(idx >> 6) * 68 + (idx & 63)] = sp[32 + lane];
        }
        if (lane < 16) {
            float4 v = ((const float4*)(ea + (size_t)base * 16))[lane];
            *(float4*)&sb[272 + (lane >> 2) * 20 + (lane & 3) * 4] = v;
        }
        __syncwarp();

        const int e   = base + g;
        const int src = ei[e];
        const int dst = ei[EE + e];
        float4 exv = *(const float4*)&g_ex[(size_t)e * 4];
        float4 dnv = *(const float4*)&g_den[(size_t)dst * 4];
        float av_[4];
        av_[0] = exv.x / (dnv.x + 1e-16f);
        av_[1] = exv.y / (dnv.y + 1e-16f);
        av_[2] = exv.z / (dnv.z + 1e-16f);
        av_[3] = exv.w / (dnv.w + 1e-16f);

        const size_t vbase = (size_t)src * 128;
        const size_t obase = (size_t)dst * 128;
#pragma unroll
        for (int j = 0; j < 4; j++) {          // j == head; lanes cover c = t*4..t*4+3
            float4 ev = make_float4(0.f, 0.f, 0.f, 0.f);
            float4 f  = make_float4(0.f, 0.f, 0.f, 0.f);
#pragma unroll
            for (int d = 0; d < 16; d++) {
                float sv  = sb[272 + g * 20 + d];
                float sbv = sb[g * 68 + j * 16 + d];
                float4 w1 = *(const float4*)&s_ev[d * 128 + j * 32 + t * 4];
                float4 w2 = *(const float4*)&s_sc[d * 32 + t * 4];
                ev.x += sv * w1.x; ev.y += sv * w1.y; ev.z += sv * w1.z; ev.w += sv * w1.w;
                f.x += sbv * w2.x; f.y += sbv * w2.y; f.z += sbv * w2.z; f.w += sbv * w2.w;
            }
            float4 v = *(const float4*)&g_val[vbase + j * 32 + t * 4];
            const float aj = av_[j];
            float mx = (v.x + ev.x) * aj * f.x;
            float my = (v.y + ev.y) * aj * f.y;
            float mz = (v.z + ev.z) * aj * f.z;
            float mw = (v.w + ev.w) * aj * f.w;
            float* op = out + obase + j * 32 + t * 4;
            asm volatile("red.global.add.v4.f32 [%0], {%1,%2,%3,%4};"
                         :: "l"(op), "f"(mx), "f"(my), "f"(mz), "f"(mw) : "memory");
        }
        __syncwarp();
    }
}

// ---------------- launcher ----------------
extern "C" void kernel_launch(void* const* d_in, const int* in_sizes, int n_in,
                              void* d_out, int out_size) {
    const float* x        = (const float*)d_in[0];
    const float* edge_attr= (const float*)d_in[1];
    const float* rbf      = (const float*)d_in[2];
    const float* sbf      = (const float*)d_in[3];
    const float* w_rbf0   = (const float*)d_in[4];
    const float* w_rbf1   = (const float*)d_in[5];
    const float* w_sbf0   = (const float*)d_in[6];
    const float* w_sbf1   = (const float*)d_in[7];
    const float* w_ek     = (const float*)d_in[8];
    const float* w_ev     = (const float*)d_in[9];
    const float* w_k      = (const float*)d_in[10];
    const float* b_k      = (const float*)d_in[11];
    const float* w_q      = (const float*)d_in[12];
    const float* b_q      = (const float*)d_in[13];
    const float* w_v      = (const float*)d_in[14];
    const float* b_v      = (const float*)d_in[15];
    const float* w_skip   = (const float*)d_in[16];
    const float* b_skip   = (const float*)d_in[17];
    const int*   edge_index = (const int*)d_in[18];
    float* out = (float*)d_out;

    static const size_t k1_smem = K1_SMEM_FLOATS * sizeof(float);
    cudaFuncSetAttribute(k_node, cudaFuncAttributeMaxDynamicSharedMemorySize, (int)k1_smem);

    k_combine_rbf<<<6, 256>>>(w_rbf0, w_rbf1);
    k_combine_sbf<<<2, 256>>>(w_sbf0, w_sbf1);

    const int k1_blocks = (NN / 32 + K1_WARPS - 1) / K1_WARPS;
    k_node<<<k1_blocks, K1_WARPS * 32, k1_smem>>>(
        x, rbf, w_k, b_k, w_q, b_q, w_v, b_v, w_skip, b_skip, w_ek, out);

    k_alpha<<<EE / 4 / 8, 256>>>(edge_attr, edge_index);

    k_msg<<<1184, 256>>>(edge_attr, sbf, edge_index, w_ev, out);
}

// round 3
// speedup vs baseline: 1.0087x; 1.0087x over previous
#include <cuda_runtime.h>
#include <cuda_fp16.h>
#include <cstdint>
#include <cstddef>

#define NN 100000
#define EE 800000

// ---------------- device scratch (static: no runtime allocation) ----------------
__device__ __half g_keyh[(size_t)NN * 128];
__device__ __half g_qryh[(size_t)NN * 128];
__device__ __half g_qkh [(size_t)NN * 64];
__device__ float  g_val[(size_t)NN * 128];
__device__ float  g_ex [(size_t)EE * 4];
__device__ float  g_den[(size_t)NN * 4];
__device__ float  g_wrbfc[42 * 32];
__device__ float  g_wsbfc[16 * 32];

// ---------------- K0: combine weight pairs ----------------
__global__ void k_combine_rbf(const float* __restrict__ w0, const float* __restrict__ w1) {
    int i = blockIdx.x * blockDim.x + threadIdx.x;
    if (i >= 42 * 32) return;
    int d = i >> 5, c = i & 31;
    float s = 0.f;
#pragma unroll
    for (int m = 0; m < 32; m++) s += w0[d * 32 + m] * w1[m * 32 + c];
    g_wrbfc[i] = s;
}

__global__ void k_combine_sbf(const float* __restrict__ w0, const float* __restrict__ w1) {
    int i = blockIdx.x * blockDim.x + threadIdx.x;
    if (i >= 16 * 32) return;
    int d = i >> 5, c = i & 31;
    float s = 0.f;
#pragma unroll
    for (int m = 0; m < 32; m++) s += w0[d * 32 + m] * w1[m * 32 + c];
    g_wsbfc[i] = s;
}

// ---------------- K1: node kernel ----------------
#define K1_WARPS 12
#define K1_SMEM_FLOATS (20288 + K1_WARPS * 1440)

__global__ void __launch_bounds__(K1_WARPS * 32)
k_node(const float* __restrict__ x, const float* __restrict__ rbf,
       const float* __restrict__ wk, const float* __restrict__ bk,
       const float* __restrict__ wq, const float* __restrict__ bq,
       const float* __restrict__ wv, const float* __restrict__ bv,
       const float* __restrict__ wsk, const float* __restrict__ bsk,
       const float* __restrict__ wek, float* __restrict__ out) {
    extern __shared__ float sh[];
    float* s_wk  = sh;
    float* s_wq  = sh + 4096;
    float* s_wv  = sh + 8192;
    float* s_ws  = sh + 12288;
    float* s_ekT = sh + 16384;   // ekT[j*16+d] = wek[d*128+j]
    float* s_rc  = sh + 18432;
    float* s_b   = sh + 19776;
    float* s_stg = sh + 20288;

    const int tid = threadIdx.x, nt = blockDim.x;
    for (int i = tid; i < 4096; i += nt) {
        s_wk[i] = wk[i]; s_wq[i] = wq[i]; s_wv[i] = wv[i]; s_ws[i] = wsk[i];
    }
    for (int i = tid; i < 2048; i += nt) {
        int j = i >> 4, d = i & 15;
        s_ekT[i] = wek[d * 128 + j];
    }
    for (int i = tid; i < 1344; i += nt) s_rc[i] = g_wrbfc[i];
    for (int i = tid; i < 512; i += nt) {
        int w = i >> 7, c = i & 127;
        s_b[i] = (w == 0) ? bk[c] : (w == 1) ? bq[c] : (w == 2) ? bv[c] : bsk[c];
    }
    __syncthreads();

    const int warpid = tid >> 5;
    const int lane   = tid & 31;
    const int tile   = blockIdx.x * K1_WARPS + warpid;
    if (tile >= (NN / 32)) return;
    const int n0 = tile * 32;
    const int n  = n0 + lane;
    float* wb = s_stg + warpid * 1440;

    // ---- stage x rows (coalesced) -> per-lane registers ----
    for (int r = 0; r < 32; r++)
        wb[r * 33 + lane] = x[(size_t)(n0 + r) * 32 + lane];
    __syncwarp();
    float xr[32];
#pragma unroll
    for (int c = 0; c < 32; c++) xr[c] = wb[lane * 33 + c];
    __syncwarp();

    // ---- stage rbf rows ----
    for (int r = 0; r < 32; r++) {
        wb[r * 45 + lane] = rbf[(size_t)(n0 + r) * 42 + lane];
        if (lane < 10) wb[r * 45 + 32 + lane] = rbf[(size_t)(n0 + r) * 42 + 32 + lane];
    }
    __syncwarp();
    float rr[42];
#pragma unroll
    for (int d = 0; d < 42; d++) rr[d] = wb[lane * 45 + d];

    // ---- rbf_filter (combined) -> x_src ----
    float xs[32];
#pragma unroll
    for (int ct8 = 0; ct8 < 8; ct8++) {
        float4 a = make_float4(0.f, 0.f, 0.f, 0.f);
#pragma unroll
        for (int d = 0; d < 42; d++) {
            float4 w = *(const float4*)&s_rc[d * 32 + ct8 * 4];
            a.x += rr[d] * w.x; a.y += rr[d] * w.y;
            a.z += rr[d] * w.z; a.w += rr[d] * w.w;
        }
        xs[ct8 * 4 + 0] = a.x * xr[ct8 * 4 + 0];
        xs[ct8 * 4 + 1] = a.y * xr[ct8 * 4 + 1];
        xs[ct8 * 4 + 2] = a.z * xr[ct8 * 4 + 2];
        xs[ct8 * 4 + 3] = a.w * xr[ct8 * 4 + 3];
    }

    // ---- main projections + folded qk ----
    float qk[16];
#pragma unroll 1
    for (int ct = 0; ct < 32; ct++) {
        const int ch = ct * 4;
        if ((ct & 7) == 0) {
#pragma unroll
            for (int i = 0; i < 16; i++) qk[i] = 0.f;
        }
        float4 ak  = *(const float4*)&s_b[ch];
        float4 aq  = *(const float4*)&s_b[128 + ch];
        float4 av  = *(const float4*)&s_b[256 + ch];
        float4 as2 = *(const float4*)&s_b[384 + ch];
#pragma unroll
        for (int c = 0; c < 32; c++) {
            float4 w1 = *(const float4*)&s_wk[c * 128 + ch];
            float4 w2 = *(const float4*)&s_wq[c * 128 + ch];
            float4 w3 = *(const float4*)&s_wv[c * 128 + ch];
            float4 w4 = *(const float4*)&s_ws[c * 128 + ch];
            float a = xs[c], b = xr[c];
            ak.x  += a * w1.x; ak.y  += a * w1.y; ak.z  += a * w1.z; ak.w  += a * w1.w;
            aq.x  += b * w2.x; aq.y  += b * w2.y; aq.z  += b * w2.z; aq.w  += b * w2.w;
            av.x  += a * w3.x; av.y  += a * w3.y; av.z  += a * w3.z; av.w  += a * w3.w;
            as2.x += b * w4.x; as2.y += b * w4.y; as2.z += b * w4.z; as2.w += b * w4.w;
        }
        // key/query stored fp16 (gathered by k_alpha)
        {
            __half2 h0 = __floats2half2_rn(ak.x, ak.y);
            __half2 h1 = __floats2half2_rn(ak.z, ak.w);
            *(uint2*)&g_keyh[(size_t)n * 128 + ch] =
                make_uint2(*(unsigned*)&h0, *(unsigned*)&h1);
            __half2 q0 = __floats2half2_rn(aq.x, aq.y);
            __half2 q1 = __floats2half2_rn(aq.z, aq.w);
            *(uint2*)&g_qryh[(size_t)n * 128 + ch] =
                make_uint2(*(unsigned*)&q0, *(unsigned*)&q1);
        }
        *(float4*)&g_val[(size_t)n * 128 + ch] = av;
        *(float4*)&out  [(size_t)n * 128 + ch] = as2;

        // qk[h][d] += q[ch+u] * ekT[(ch+u)*16 + d]
        float qa[4] = {aq.x, aq.y, aq.z, aq.w};
#pragma unroll
        for (int u = 0; u < 4; u++) {
#pragma unroll
            for (int dt = 0; dt < 4; dt++) {
                float4 ekv = *(const float4*)&s_ekT[(ch + u) * 16 + dt * 4];
                qk[dt * 4 + 0] += qa[u] * ekv.x;
                qk[dt * 4 + 1] += qa[u] * ekv.y;
                qk[dt * 4 + 2] += qa[u] * ekv.z;
                qk[dt * 4 + 3] += qa[u] * ekv.w;
            }
        }
        if ((ct & 7) == 7) {
            const int h = ct >> 3;
            unsigned uu[8];
#pragma unroll
            for (int i = 0; i < 8; i++) {
                __half2 p = __floats2half2_rn(qk[2 * i], qk[2 * i + 1]);
                uu[i] = *(unsigned*)&p;
            }
            *(uint4*)&g_qkh[(size_t)n * 64 + h * 16] =
                make_uint4(uu[0], uu[1], uu[2], uu[3]);
            *(uint4*)&g_qkh[(size_t)n * 64 + h * 16 + 8] =
                make_uint4(uu[4], uu[5], uu[6], uu[7]);
        }
    }
    *(float4*)&g_den[(size_t)n * 4] = make_float4(0.f, 0.f, 0.f, 0.f);
}

// ---------------- K2: edge alpha (8 lanes/edge, 4 edges/warp, fp16 gathers) ----------------
__global__ void __launch_bounds__(256)
k_alpha(const float* __restrict__ ea, const int* __restrict__ ei) {
    const int gw   = (blockIdx.x * blockDim.x + threadIdx.x) >> 5;
    const int lane = threadIdx.x & 31;
    const int g = lane >> 3, t = lane & 7;
    const int e = gw * 4 + g;
    if (e >= EE) return;
    const int src = ei[e];
    const int dst = ei[EE + e];
    const int h = t >> 1, half = t & 1;

    const uint4* qp = (const uint4*)(g_qryh + (size_t)dst * 128 + h * 32 + half * 16);
    const uint4* kp = (const uint4*)(g_keyh + (size_t)src * 128 + h * 32 + half * 16);
    float s = 0.f;
#pragma unroll
    for (int b = 0; b < 2; b++) {
        uint4 qv = qp[b], kv = kp[b];
        const __half2* qh = (const __half2*)&qv;
        const __half2* kh = (const __half2*)&kv;
#pragma unroll
        for (int i = 0; i < 4; i++) {
            float2 q2 = __half22float2(qh[i]);
            float2 k2 = __half22float2(kh[i]);
            s += q2.x * k2.x + q2.y * k2.y;
        }
    }
    uint4 qkv = *(const uint4*)(g_qkh + (size_t)dst * 64 + h * 16 + half * 8);
    const __half2* qkh = (const __half2*)&qkv;
    const float4* eap = (const float4*)(ea + (size_t)e * 16 + half * 8);
    float4 e0 = eap[0], e1 = eap[1];
    float2 a;
    a = __half22float2(qkh[0]); s += a.x * e0.x + a.y * e0.y;
    a = __half22float2(qkh[1]); s += a.x * e0.z + a.y * e0.w;
    a = __half22float2(qkh[2]); s += a.x * e1.x + a.y * e1.y;
    a = __half22float2(qkh[3]); s += a.x * e1.z + a.y * e1.w;

    s += __shfl_xor_sync(0xffffffffu, s, 1);
    if (half == 0) {
        float ex = __expf(s * 0.17677669529663687f);  // 1/sqrt(32)
        g_ex[(size_t)e * 4 + h] = ex;
        atomicAdd(&g_den[(size_t)dst * 4 + h], ex);
    }
}

// ---------------- K3: message + aggregation (8 lanes/edge, 4 edges/warp) ----------------
__global__ void __launch_bounds__(256)
k_msg(const float* __restrict__ ea, const float* __restrict__ sbf,
      const int* __restrict__ ei, const float* __restrict__ wev,
      float* __restrict__ out) {
    __shared__ float s_ev[16 * 128];
    __shared__ float s_sc[16 * 32];
    __shared__ float s_buf[8][368];   // per warp: sbf 4 edges x 64 @pitch72 (=288), ea 4x16 @pitch20 (=80)

    for (int i = threadIdx.x; i < 2048; i += 256) s_ev[i] = wev[i];
    for (int i = threadIdx.x; i < 512;  i += 256) s_sc[i] = g_wsbfc[i];
    __syncthreads();

    const int warpid = threadIdx.x >> 5;
    const int lane   = threadIdx.x & 31;
    const int g = lane >> 3, t = lane & 7;
    const int warps_total = gridDim.x * 8;
    float* sb = s_buf[warpid];

    for (int tile = blockIdx.x * 8 + warpid; tile < EE / 4; tile += warps_total) {
        const int base = tile * 4;
        // stage sbf (4 edges x 64 floats, contiguous in gmem), pitch 72 keeps 16B alignment
        const float4* sp = (const float4*)(sbf + (size_t)base * 64);
        {
            int idx = lane * 4;                // elems 0..127
            *(float4*)&sb[(idx >> 6) * 72 + (idx & 63)] = sp[lane];
            idx = 128 + lane * 4;              // elems 128..255
            *(float4*)&sb[(idx >> 6) * 72 + (idx & 63)] = sp[32 + lane];
        }
        if (lane < 16) {
            float4 v = ((const float4*)(ea + (size_t)base * 16))[lane];
            *(float4*)&sb[288 + (lane >> 2) * 20 + (lane & 3) * 4] = v;
        }
        __syncwarp();

        const int e   = base + g;
        const int src = ei[e];
        const int dst = ei[EE + e];
        float4 exv = *(const float4*)&g_ex[(size_t)e * 4];
        float4 dnv = *(const float4*)&g_den[(size_t)dst * 4];
        float av_[4];
        av_[0] = exv.x / (dnv.x + 1e-16f);
        av_[1] = exv.y / (dnv.y + 1e-16f);
        av_[2] = exv.z / (dnv.z + 1e-16f);
        av_[3] = exv.w / (dnv.w + 1e-16f);

        // accumulate edge_val and sbf_filter, d-outer so sv/w2 are hoisted
        float4 aev[4], af[4];
#pragma unroll
        for (int j = 0; j < 4; j++) {
            aev[j] = make_float4(0.f, 0.f, 0.f, 0.f);
            af[j]  = make_float4(0.f, 0.f, 0.f, 0.f);
        }
#pragma unroll
        for (int d = 0; d < 16; d++) {
            float sv  = sb[288 + g * 20 + d];
            float4 w2 = *(const float4*)&s_sc[d * 32 + t * 4];
#pragma unroll
            for (int j = 0; j < 4; j++) {
                float sbv = sb[g * 72 + j * 16 + d];
                float4 w1 = *(const float4*)&s_ev[d * 128 + j * 32 + t * 4];
                aev[j].x += sv * w1.x; aev[j].y += sv * w1.y;
                aev[j].z += sv * w1.z; aev[j].w += sv * w1.w;
                af[j].x += sbv * w2.x; af[j].y += sbv * w2.y;
                af[j].z += sbv * w2.z; af[j].w += sbv * w2.w;
            }
        }

        const size_t vbase = (size_t)src * 128;
        const size_t obase = (size_t)dst * 128;
#pragma unroll
        for (int j = 0; j < 4; j++) {
            float4 v = *(const float4*)&g_val[vbase + j * 32 + t * 4];
            const float aj = av_[j];
            float mx = (v.x + aev[j].x) * aj * af[j].x;
            float my = (v.y + aev[j].y) * aj * af[j].y;
            float mz = (v.z + aev[j].z) * aj * af[j].z;
            float mw = (v.w + aev[j].w) * aj * af[j].w;
            float* op = out + obase + j * 32 + t * 4;
            asm volatile("red.global.add.v4.f32 [%0], {%1,%2,%3,%4};"
                         :: "l"(op), "f"(mx), "f"(my), "f"(mz), "f"(mw) : "memory");
        }
        __syncwarp();
    }
}

// ---------------- launcher ----------------
extern "C" void kernel_launch(void* const* d_in, const int* in_sizes, int n_in,
                              void* d_out, int out_size) {
    const float* x        = (const float*)d_in[0];
    const float* edge_attr= (const float*)d_in[1];
    const float* rbf      = (const float*)d_in[2];
    const float* sbf      = (const float*)d_in[3];
    const float* w_rbf0   = (const float*)d_in[4];
    const float* w_rbf1   = (const float*)d_in[5];
    const float* w_sbf0   = (const float*)d_in[6];
    const float* w_sbf1   = (const float*)d_in[7];
    const float* w_ek     = (const float*)d_in[8];
    const float* w_ev     = (const float*)d_in[9];
    const float* w_k      = (const float*)d_in[10];
    const float* b_k      = (const float*)d_in[11];
    const float* w_q      = (const float*)d_in[12];
    const float* b_q      = (const float*)d_in[13];
    const float* w_v      = (const float*)d_in[14];
    const float* b_v      = (const float*)d_in[15];
    const float* w_skip   = (const float*)d_in[16];
    const float* b_skip   = (const float*)d_in[17];
    const int*   edge_index = (const int*)d_in[18];
    float* out = (float*)d_out;

    static const size_t k1_smem = K1_SMEM_FLOATS * sizeof(float);
    cudaFuncSetAttribute(k_node, cudaFuncAttributeMaxDynamicSharedMemorySize, (int)k1_smem);

    k_combine_rbf<<<6, 256>>>(w_rbf0, w_rbf1);
    k_combine_sbf<<<2, 256>>>(w_sbf0, w_sbf1);

    const int k1_blocks = (NN / 32 + K1_WARPS - 1) / K1_WARPS;
    k_node<<<k1_blocks, K1_WARPS * 32, k1_smem>>>(
        x, rbf, w_k, b_k, w_q, b_q, w_v, b_v, w_skip, b_skip, w_ek, out);

    k_alpha<<<EE / 4 / 8, 256>>>(edge_attr, edge_index);

    k_msg<<<1184, 256>>>(edge_attr, sbf, edge_index, w_ev, out);
}